// round 5
// baseline (speedup 1.0000x reference)
#include <cuda_runtime.h>
#include <cstddef>
#include <math.h>

// Quant-aware attention, engineered to bit-match the JAX/XLA reference.
//   - QK and PV: sequential fp32 FFMA over contraction dim, ascending order.
//     (R1/R2 evidence: ref GEMM rounding is chain-like. DO NOT REORDER.)
//   - exp: CUDA expf (== libdevice __nv_expf, what XLA emits on GPU).
//   - softmax row sum: XLA:GPU default row-reduce association for row=1024:
//     one element per virtual thread; halves-first tree over each contiguous
//     32-block; halves-first tree over the 32 block partials.
//   fq(x,s) = clip(rint(x/s), -128, 127) * s in f32 (IEEE div, half-even rint).

#define S_LEN 1024
#define HD 64
#define QT 32           // query rows per CTA
#define KT 128          // K/V rows per smem tile
#define SC_STRIDE 1028  // scores row stride (floats), 16B-aligned rows
#define QS_STRIDE 68    // Q tile row stride (floats)
#define KS_STRIDE 68    // K/V tile row stride (floats)

#define SMEM_FLOATS (QT*SC_STRIDE + QT*QS_STRIDE + KT*KS_STRIDE)

__device__ __forceinline__ float fq(float x, float s) {
    float r = rintf(__fdiv_rn(x, s));        // IEEE f32 div + round-half-even
    r = fminf(fmaxf(r, -128.0f), 127.0f);
    return r * s;
}

__global__ __launch_bounds__(256, 1)
void attn_qat_kernel(const float* __restrict__ Q,
                     const float* __restrict__ K,
                     const float* __restrict__ V,
                     const float* __restrict__ qk_s_p,
                     const float* __restrict__ a_s_p,
                     const float* __restrict__ av_s_p,
                     float* __restrict__ O) {
    extern __shared__ float smem[];
    float* SC  = smem;                       // [QT][SC_STRIDE] scores / probs
    float* Qs  = SC + QT * SC_STRIDE;        // [QT][QS_STRIDE]
    float* KVs = Qs + QT * QS_STRIDE;        // [KT][KS_STRIDE] K tile, then V tile

    const int tid   = threadIdx.x;
    const int bh    = blockIdx.y;
    const int qbase = blockIdx.x * QT;

    const float qk_s = *qk_s_p;
    const float a_s  = *a_s_p;
    const float av_s = *av_s_p;

    const float* Qg = Q + ((size_t)bh * S_LEN + qbase) * HD;
    const float* Kg = K + (size_t)bh * S_LEN * HD;
    const float* Vg = V + (size_t)bh * S_LEN * HD;

    // ---- load Q tile (32 x 64) ----
    #pragma unroll
    for (int it = 0; it < 2; it++) {
        int lin = it * 256 + tid;            // 512 float4
        int q  = lin >> 4;
        int dq = lin & 15;
        float4 v = *(const float4*)(Qg + q * HD + dq * 4);
        *(float4*)(Qs + q * QS_STRIDE + dq * 4) = v;
    }

    // ===== Phase 1: S = fq((Q K^T)/8), sequential fp32 FFMA ascending d =====
    {
        const int tk = tid & 31;
        const int tq = tid >> 5;
        const int q0 = tq * 4;

        for (int kt = 0; kt < S_LEN / KT; kt++) {
            __syncthreads();
            #pragma unroll
            for (int it = 0; it < 8; it++) { // 2048 float4 = 128x64
                int lin = it * 256 + tid;
                int k  = lin >> 4;
                int dq = lin & 15;
                float4 v = *(const float4*)(Kg + (kt * KT + k) * HD + dq * 4);
                *(float4*)(KVs + k * KS_STRIDE + dq * 4) = v;
            }
            __syncthreads();

            float acc[4][4];
            #pragma unroll
            for (int i = 0; i < 4; i++)
                #pragma unroll
                for (int j = 0; j < 4; j++) acc[i][j] = 0.0f;

            #pragma unroll
            for (int d = 0; d < HD; d += 4) {
                float4 qv[4], kv[4];
                #pragma unroll
                for (int i = 0; i < 4; i++)
                    qv[i] = *(const float4*)(Qs + (q0 + i) * QS_STRIDE + d);
                #pragma unroll
                for (int j = 0; j < 4; j++)
                    kv[j] = *(const float4*)(KVs + (tk + 32 * j) * KS_STRIDE + d);
                #pragma unroll
                for (int i = 0; i < 4; i++)
                    #pragma unroll
                    for (int j = 0; j < 4; j++) {
                        acc[i][j] += qv[i].x * kv[j].x;   // FFMA, ascending d
                        acc[i][j] += qv[i].y * kv[j].y;
                        acc[i][j] += qv[i].z * kv[j].z;
                        acc[i][j] += qv[i].w * kv[j].w;
                    }
            }

            #pragma unroll
            for (int i = 0; i < 4; i++)
                #pragma unroll
                for (int j = 0; j < 4; j++) {
                    float s = acc[i][j] * 0.125f;   // == /8 exactly
                    SC[(q0 + i) * SC_STRIDE + kt * KT + tk + 32 * j] = fq(s, qk_s);
                }
        }
    }
    __syncthreads();

    // ===== Phase 2: softmax + fq(a) — XLA:GPU default reduce association ====
    {
        const int lane = tid & 31;
        const int w    = tid >> 5;           // 8 warps, 4 rows each

        // (a) per-row max (order independent) + exp via expf (== __nv_expf)
        #pragma unroll
        for (int r = 0; r < 4; r++) {
            float* row = SC + (w * 4 + r) * SC_STRIDE;

            float m = -1e30f;
            for (int t = lane; t < S_LEN; t += 32) m = fmaxf(m, row[t]);
            #pragma unroll
            for (int o = 16; o; o >>= 1) m = fmaxf(m, __shfl_xor_sync(0xffffffffu, m, o));

            for (int t = lane; t < S_LEN; t += 32) {
                float d = row[t] - m;                    // exact f32 op
                row[t] = expf(d);                        // libdevice __nv_expf
            }
        }
        __syncwarp();

        // (b) row sum — XLA:GPU 1024-thread row-reduce association:
        //     block partial B_l = halves-first tree over contiguous 32 elems
        //     [32l, 32l+32); total = halves-first tree over B_0..B_31.
        //     (xor-shuffle tree == down-tree pairing; all lanes identical bits)
        #pragma unroll
        for (int r = 0; r < 4; r++) {
            float* row = SC + (w * 4 + r) * SC_STRIDE;

            float x[32];
            const float4* src = (const float4*)(row + 32 * lane);
            #pragma unroll
            for (int j = 0; j < 8; j++) {
                float4 v = src[j];
                x[4*j+0] = v.x; x[4*j+1] = v.y; x[4*j+2] = v.z; x[4*j+3] = v.w;
            }
            #pragma unroll
            for (int h = 16; h >= 1; h >>= 1)
                #pragma unroll
                for (int i = 0; i < 16; i++)
                    if (i < h) x[i] = x[i] + x[i + h];   // halves-first in-block
            float p = x[0];
            #pragma unroll
            for (int o = 16; o; o >>= 1)
                p += __shfl_xor_sync(0xffffffffu, p, o); // halves-first over blocks
            float sum_f = p;

            // (c) p = e/sum (IEEE div), then fake-quant
            for (int t = lane; t < S_LEN; t += 32) {
                float pr = __fdiv_rn(row[t], sum_f);
                float n = rintf(__fdiv_rn(pr, a_s));
                n = fminf(fmaxf(n, -128.0f), 127.0f);
                row[t] = n * a_s;
            }
        }
    }
    __syncthreads();

    // ===== Phase 3: O = fq(A V), sequential fp32 FFMA ascending t ============
    {
        const int tdd = tid & 15;
        const int tqq = tid >> 4;
        const int d0  = tdd * 4;
        const int q0  = tqq * 2;

        float4 o0 = make_float4(0.f, 0.f, 0.f, 0.f);
        float4 o1 = make_float4(0.f, 0.f, 0.f, 0.f);

        for (int vt = 0; vt < S_LEN / KT; vt++) {
            #pragma unroll
            for (int it = 0; it < 8; it++) {
                int lin = it * 256 + tid;
                int k  = lin >> 4;
                int dq = lin & 15;
                float4 v = *(const float4*)(Vg + (vt * KT + k) * HD + dq * 4);
                *(float4*)(KVs + k * KS_STRIDE + dq * 4) = v;
            }
            __syncthreads();

            const float* r0 = SC + q0 * SC_STRIDE + vt * KT;
            const float* r1 = r0 + SC_STRIDE;
            #pragma unroll 4
            for (int kk = 0; kk < KT; kk++) {
                float a0 = r0[kk];
                float a1 = r1[kk];
                float4 vv = *(const float4*)(KVs + kk * KS_STRIDE + d0);
                o0.x += a0 * vv.x; o0.y += a0 * vv.y; o0.z += a0 * vv.z; o0.w += a0 * vv.w;
                o1.x += a1 * vv.x; o1.y += a1 * vv.y; o1.z += a1 * vv.z; o1.w += a1 * vv.w;
            }
            __syncthreads();
        }

        float4 res0, res1;
        res0.x = fq(o0.x, av_s); res0.y = fq(o0.y, av_s);
        res0.z = fq(o0.z, av_s); res0.w = fq(o0.w, av_s);
        res1.x = fq(o1.x, av_s); res1.y = fq(o1.y, av_s);
        res1.z = fq(o1.z, av_s); res1.w = fq(o1.w, av_s);

        float* Og = O + ((size_t)bh * S_LEN + qbase + q0) * HD + d0;
        *(float4*)Og        = res0;
        *(float4*)(Og + HD) = res1;
    }
}

extern "C" void kernel_launch(void* const* d_in, const int* in_sizes, int n_in,
                              void* d_out, int out_size) {
    const float* Q    = (const float*)d_in[0];
    const float* K    = (const float*)d_in[1];
    const float* V    = (const float*)d_in[2];
    const float* qk_s = (const float*)d_in[3];
    const float* a_s  = (const float*)d_in[4];
    const float* av_s = (const float*)d_in[5];
    float* O = (float*)d_out;

    const int BH = in_sizes[0] / (S_LEN * HD);   // 128

    size_t smem = (size_t)SMEM_FLOATS * sizeof(float);   // ~175 KB
    cudaFuncSetAttribute(attn_qat_kernel,
                         cudaFuncAttributeMaxDynamicSharedMemorySize, (int)smem);

    dim3 grid(S_LEN / QT, BH);
    attn_qat_kernel<<<grid, 256, smem>>>(Q, K, V, qk_s, a_s, av_s, O);
}

// round 7
// speedup vs baseline: 1.1131x; 1.1131x over previous
#include <cuda_runtime.h>
#include <cstddef>
#include <cstdint>
#include <math.h>

// Quant-aware attention, bit-matched to the JAX/XLA reference (rel_err == 0.0
// established in R5). SACRED, DO NOT REORDER:
//   - QK and PV: sequential fp32 FMA chain over contraction dim, ascending.
//     (PV uses fma.rn.f32x2: each half is an independent IEEE f32 chain.)
//   - exp: CUDA expf (libdevice __nv_expf).
//   - softmax row sum: halves-first tree over each contiguous 32-block, then
//     halves-first tree over the 32 block partials.
//   fq(x,s) = clip(rint(x/s), -128, 127) * s in f32 (IEEE div, half-even rint).
// R6/R7 perf changes (bit-neutral): cp.async double-buffered K/V tiles;
// phase-3 retile to 4q x 4d on 128 threads with packed f32x2 FMA; loader warps.

#define S_LEN 1024
#define HD 64
#define QT 32           // query rows per CTA
#define KT 128          // K/V rows per smem tile
#define SC_STRIDE 1028  // scores row stride (floats), 16B-aligned rows
#define QS_STRIDE 68    // Q tile row stride (floats)
#define KS_STRIDE 68    // K/V tile row stride (floats)
#define KV_TILE  (KT*KS_STRIDE)

#define SMEM_FLOATS (QT*SC_STRIDE + QT*QS_STRIDE + 2*KV_TILE)

typedef unsigned long long ull;
typedef unsigned int u32;

__device__ __forceinline__ float fq(float x, float s) {
    float r = rintf(__fdiv_rn(x, s));        // IEEE f32 div + round-half-even
    r = fminf(fmaxf(r, -128.0f), 127.0f);
    return r * s;
}

__device__ __forceinline__ ull ffma2(ull a, ull b, ull c) {
    ull d;
    asm("fma.rn.f32x2 %0, %1, %2, %3;" : "=l"(d) : "l"(a), "l"(b), "l"(c));
    return d;
}
__device__ __forceinline__ ull pack2(float x, float y) {
    ull r; asm("mov.b64 %0, {%1, %2};" : "=l"(r) : "f"(x), "f"(y)); return r;
}
__device__ __forceinline__ void unpack2(ull v, float& lo, float& hi) {
    asm("mov.b64 {%0, %1}, %2;" : "=f"(lo), "=f"(hi) : "l"(v));
}

__device__ __forceinline__ void cp16(u32 s, const void* g) {
    asm volatile("cp.async.cg.shared.global [%0], [%1], 16;" :: "r"(s), "l"(g));
}
#define CP_COMMIT() asm volatile("cp.async.commit_group;")
#define CP_WAIT1()  asm volatile("cp.async.wait_group 1;")
#define CP_WAIT0()  asm volatile("cp.async.wait_group 0;")

__global__ __launch_bounds__(256, 1)
void attn_qat_kernel(const float* __restrict__ Q,
                     const float* __restrict__ K,
                     const float* __restrict__ V,
                     const float* __restrict__ qk_s_p,
                     const float* __restrict__ a_s_p,
                     const float* __restrict__ av_s_p,
                     float* __restrict__ O) {
    extern __shared__ float smem[];
    float* SC  = smem;                       // [QT][SC_STRIDE] scores / probs
    float* Qs  = SC + QT * SC_STRIDE;        // [QT][QS_STRIDE]
    float* KVs = Qs + QT * QS_STRIDE;        // [2][KT][KS_STRIDE] double buffer

    const int tid   = threadIdx.x;
    const int bh    = blockIdx.y;
    const int qbase = blockIdx.x * QT;

    const float qk_s = *qk_s_p;
    const float a_s  = *a_s_p;
    const float av_s = *av_s_p;

    const float* Qg = Q + ((size_t)bh * S_LEN + qbase) * HD;
    const float* Kg = K + (size_t)bh * S_LEN * HD;
    const float* Vg = V + (size_t)bh * S_LEN * HD;

    const u32 kvs_u32 = (u32)__cvta_generic_to_shared(KVs);

    // ---- prologue: async-load K tile 0, plus Q tile via regular LDG/STS ----
    {
        #pragma unroll
        for (int it = 0; it < 8; it++) {     // 2048 float4 over 256 threads
            int lin = it * 256 + tid;
            int k  = lin >> 4;
            int dq = lin & 15;
            cp16(kvs_u32 + (u32)((k * KS_STRIDE + dq * 4) * 4),
                 Kg + k * HD + dq * 4);
        }
        CP_COMMIT();
        #pragma unroll
        for (int it = 0; it < 2; it++) {     // Q: 512 float4
            int lin = it * 256 + tid;
            int q  = lin >> 4;
            int dq = lin & 15;
            float4 v = *(const float4*)(Qg + q * HD + dq * 4);
            *(float4*)(Qs + q * QS_STRIDE + dq * 4) = v;
        }
    }

    // ===== Phase 1: S = fq((Q K^T)/8), sequential fp32 FFMA ascending d =====
    {
        const int tk = tid & 31;
        const int tq = tid >> 5;
        const int q0 = tq * 4;

        for (int kt = 0; kt < S_LEN / KT; kt++) {
            const int cur = kt & 1;
            if (kt < 7) {                    // prefetch next K tile
                const float* src = Kg + (kt + 1) * KT * HD;
                u32 dst = kvs_u32 + (u32)((1 - cur) * KV_TILE * 4);
                #pragma unroll
                for (int it = 0; it < 8; it++) {
                    int lin = it * 256 + tid;
                    int k  = lin >> 4;
                    int dq = lin & 15;
                    cp16(dst + (u32)((k * KS_STRIDE + dq * 4) * 4),
                         src + k * HD + dq * 4);
                }
                CP_COMMIT();
                CP_WAIT1();
            } else {
                CP_WAIT0();
            }
            __syncthreads();

            const float* Kt = KVs + cur * KV_TILE;

            float acc[4][4];
            #pragma unroll
            for (int i = 0; i < 4; i++)
                #pragma unroll
                for (int j = 0; j < 4; j++) acc[i][j] = 0.0f;

            #pragma unroll
            for (int d = 0; d < HD; d += 4) {
                float4 qv[4], kv[4];
                #pragma unroll
                for (int i = 0; i < 4; i++)
                    qv[i] = *(const float4*)(Qs + (q0 + i) * QS_STRIDE + d);
                #pragma unroll
                for (int j = 0; j < 4; j++)
                    kv[j] = *(const float4*)(Kt + (tk + 32 * j) * KS_STRIDE + d);
                #pragma unroll
                for (int i = 0; i < 4; i++)
                    #pragma unroll
                    for (int j = 0; j < 4; j++) {
                        acc[i][j] += qv[i].x * kv[j].x;   // FFMA, ascending d
                        acc[i][j] += qv[i].y * kv[j].y;
                        acc[i][j] += qv[i].z * kv[j].z;
                        acc[i][j] += qv[i].w * kv[j].w;
                    }
            }

            #pragma unroll
            for (int i = 0; i < 4; i++)
                #pragma unroll
                for (int j = 0; j < 4; j++) {
                    float s = acc[i][j] * 0.125f;   // == /8 exactly
                    SC[(q0 + i) * SC_STRIDE + kt * KT + tk + 32 * j] = fq(s, qk_s);
                }
            __syncthreads();                 // all done with buf cur before reuse
        }
    }

    // ===== Phase 2: softmax + fq(a) — R5 bit-exact reduce association =======
    {
        const int lane = tid & 31;
        const int w    = tid >> 5;           // 8 warps, 4 rows each

        #pragma unroll
        for (int r = 0; r < 4; r++) {
            float* row = SC + (w * 4 + r) * SC_STRIDE;

            float m = -1e30f;
            for (int t = lane; t < S_LEN; t += 32) m = fmaxf(m, row[t]);
            #pragma unroll
            for (int o = 16; o; o >>= 1) m = fmaxf(m, __shfl_xor_sync(0xffffffffu, m, o));

            for (int t = lane; t < S_LEN; t += 32) {
                float d = row[t] - m;                    // exact f32 op
                row[t] = expf(d);                        // libdevice __nv_expf
            }
        }
        __syncwarp();

        #pragma unroll
        for (int r = 0; r < 4; r++) {
            float* row = SC + (w * 4 + r) * SC_STRIDE;

            float x[32];
            const float4* src = (const float4*)(row + 32 * lane);
            #pragma unroll
            for (int j = 0; j < 8; j++) {
                float4 v = src[j];
                x[4*j+0] = v.x; x[4*j+1] = v.y; x[4*j+2] = v.z; x[4*j+3] = v.w;
            }
            #pragma unroll
            for (int h = 16; h >= 1; h >>= 1)
                #pragma unroll
                for (int i = 0; i < 16; i++)
                    if (i < h) x[i] = x[i] + x[i + h];   // halves-first in-block
            float p = x[0];
            #pragma unroll
            for (int o = 16; o; o >>= 1)
                p += __shfl_xor_sync(0xffffffffu, p, o); // halves-first over blocks
            float sum_f = p;

            for (int t = lane; t < S_LEN; t += 32) {
                float pr = __fdiv_rn(row[t], sum_f);
                float n = rintf(__fdiv_rn(pr, a_s));
                n = fminf(fmaxf(n, -128.0f), 127.0f);
                row[t] = n * a_s;
            }
        }
    }

    // ---- prologue for phase 3: loader warps (tid>=128) async-load V tile 0 --
    if (tid >= 128) {
        const int lt = tid - 128;
        #pragma unroll
        for (int it = 0; it < 16; it++) {    // 2048 float4 over 128 threads
            int lin = it * 128 + lt;
            int k  = lin >> 4;
            int dq = lin & 15;
            cp16(kvs_u32 + (u32)((k * KS_STRIDE + dq * 4) * 4),
                 Vg + k * HD + dq * 4);
        }
        CP_COMMIT();
    }

    // ===== Phase 3: O = fq(A V), f32x2 chains ascending t, 4q x 4d ==========
    {
        const int td = tid & 15;             // 16 d-groups of 4
        const int tq = tid >> 4;             // 8 q-groups of 4 (tid<128)
        const int d0 = td * 4;
        const int q0 = tq * 4;

        ull acc[4][2];
        #pragma unroll
        for (int i = 0; i < 4; i++) { acc[i][0] = pack2(0.f, 0.f); acc[i][1] = pack2(0.f, 0.f); }

        for (int vt = 0; vt < S_LEN / KT; vt++) {
            const int cur = vt & 1;
            if (tid >= 128 && vt < 7) {      // prefetch next V tile
                const int lt = tid - 128;
                const float* src = Vg + (vt + 1) * KT * HD;
                u32 dst = kvs_u32 + (u32)((1 - cur) * KV_TILE * 4);
                #pragma unroll
                for (int it = 0; it < 16; it++) {
                    int lin = it * 128 + lt;
                    int k  = lin >> 4;
                    int dq = lin & 15;
                    cp16(dst + (u32)((k * KS_STRIDE + dq * 4) * 4),
                         src + k * HD + dq * 4);
                }
                CP_COMMIT();
            }
            if (vt < 7) CP_WAIT1(); else CP_WAIT0();
            __syncthreads();

            if (tid < 128) {
                const float* Vt = KVs + cur * KV_TILE;
                const float* r0 = SC + (q0 + 0) * SC_STRIDE + vt * KT;
                const float* r1 = SC + (q0 + 1) * SC_STRIDE + vt * KT;
                const float* r2 = SC + (q0 + 2) * SC_STRIDE + vt * KT;
                const float* r3 = SC + (q0 + 3) * SC_STRIDE + vt * KT;
                #pragma unroll 4
                for (int kk = 0; kk < KT; kk++) {
                    float a0 = r0[kk], a1 = r1[kk], a2 = r2[kk], a3 = r3[kk];
                    ull A0 = pack2(a0, a0), A1 = pack2(a1, a1);
                    ull A2 = pack2(a2, a2), A3 = pack2(a3, a3);
                    ulonglong2 vv = *(const ulonglong2*)(Vt + kk * KS_STRIDE + d0);
                    acc[0][0] = ffma2(A0, vv.x, acc[0][0]);
                    acc[0][1] = ffma2(A0, vv.y, acc[0][1]);
                    acc[1][0] = ffma2(A1, vv.x, acc[1][0]);
                    acc[1][1] = ffma2(A1, vv.y, acc[1][1]);
                    acc[2][0] = ffma2(A2, vv.x, acc[2][0]);
                    acc[2][1] = ffma2(A2, vv.y, acc[2][1]);
                    acc[3][0] = ffma2(A3, vv.x, acc[3][0]);
                    acc[3][1] = ffma2(A3, vv.y, acc[3][1]);
                }
            }
            __syncthreads();                 // all done with buf cur before reuse
        }

        if (tid < 128) {
            #pragma unroll
            for (int i = 0; i < 4; i++) {
                float v0, v1, v2, v3;
                unpack2(acc[i][0], v0, v1);
                unpack2(acc[i][1], v2, v3);
                float4 res;
                res.x = fq(v0, av_s); res.y = fq(v1, av_s);
                res.z = fq(v2, av_s); res.w = fq(v3, av_s);
                float* Og = O + ((size_t)bh * S_LEN + qbase + q0 + i) * HD + d0;
                *(float4*)Og = res;
            }
        }
    }
}

extern "C" void kernel_launch(void* const* d_in, const int* in_sizes, int n_in,
                              void* d_out, int out_size) {
    const float* Q    = (const float*)d_in[0];
    const float* K    = (const float*)d_in[1];
    const float* V    = (const float*)d_in[2];
    const float* qk_s = (const float*)d_in[3];
    const float* a_s  = (const float*)d_in[4];
    const float* av_s = (const float*)d_in[5];
    float* O = (float*)d_out;

    const int BH = in_sizes[0] / (S_LEN * HD);   // 128

    size_t smem = (size_t)SMEM_FLOATS * sizeof(float);   // ~205 KB
    cudaFuncSetAttribute(attn_qat_kernel,
                         cudaFuncAttributeMaxDynamicSharedMemorySize, (int)smem);

    dim3 grid(S_LEN / QT, BH);
    attn_qat_kernel<<<grid, 256, smem>>>(Q, K, V, qk_s, a_s, av_s, O);
}

// round 8
// speedup vs baseline: 1.3686x; 1.2296x over previous
#include <cuda_runtime.h>
#include <cstddef>
#include <cstdint>
#include <math.h>

// Quant-aware attention, bit-matched to the JAX/XLA reference (rel_err == 0.0).
// SACRED (do not reorder): QK/PV sequential fp32 FMA chains ascending over the
// contraction dim (f32x2 halves are independent IEEE chains); expf; softmax sum
// = halves-first tree within each contiguous 32-block then halves-first tree
// over the 32 block partials; IEEE f32 divs; rintf; clamp.
// R8: scores/probs stored as int8 codes (values are n*scale on the quant grid;
// dequant I2F+FMUL is bitwise identical to the f32 path). smem 112KB -> 2 CTAs
// per SM. Phase-1 f32x2 (q-row pairs). Phase-3 packed A loads + inline dequant.

#define S_LEN 1024
#define HD 64
#define QT 32
#define KT 128
#define SCB 1056          // SC row stride in BYTES (int8 codes), 16B-aligned
#define QS_STRIDE 68      // floats
#define KS_STRIDE 68      // floats
#define KV_TILE  (KT*KS_STRIDE)          // floats
#define SC_BYTES (QT*SCB)                // 33792
#define SMEM_BYTES (SC_BYTES + 4*(QT*QS_STRIDE) + 4*(2*KV_TILE))  // 112128

typedef unsigned long long ull;
typedef unsigned int u32;

__device__ __forceinline__ ull ffma2(ull a, ull b, ull c) {
    ull d;
    asm("fma.rn.f32x2 %0, %1, %2, %3;" : "=l"(d) : "l"(a), "l"(b), "l"(c));
    return d;
}
__device__ __forceinline__ ull pack2(float x, float y) {
    ull r; asm("mov.b64 %0, {%1, %2};" : "=l"(r) : "f"(x), "f"(y)); return r;
}
__device__ __forceinline__ void unpack2(ull v, float& lo, float& hi) {
    asm("mov.b64 {%0, %1}, %2;" : "=f"(lo), "=f"(hi) : "l"(v));
}
__device__ __forceinline__ void cp16(u32 s, const void* g) {
    asm volatile("cp.async.cg.shared.global [%0], [%1], 16;" :: "r"(s), "l"(g));
}
#define CP_COMMIT() asm volatile("cp.async.commit_group;")
#define CP_WAIT1()  asm volatile("cp.async.wait_group 1;")
#define CP_WAIT0()  asm volatile("cp.async.wait_group 0;")

// quantize to int8 code: n = clip(rint(x/s), -128, 127)  (IEEE div, half-even)
__device__ __forceinline__ int q8(float x, float s) {
    float r = rintf(__fdiv_rn(x, s));
    r = fminf(fmaxf(r, -128.0f), 127.0f);
    return (int)r;
}
// byte b (0..3) of word w -> float (exact) ; dequant = *scale elsewhere
__device__ __forceinline__ float b2f(int w, int b) {
    return (float)((int)(signed char)(w >> (8 * b)));
}

__global__ __launch_bounds__(256, 2)
void attn_qat_kernel(const float* __restrict__ Q,
                     const float* __restrict__ K,
                     const float* __restrict__ V,
                     const float* __restrict__ qk_s_p,
                     const float* __restrict__ a_s_p,
                     const float* __restrict__ av_s_p,
                     float* __restrict__ O) {
    extern __shared__ float smem[];
    char*  SCc = (char*)smem;                         // [QT][SCB] int8 codes
    float* Qs  = (float*)((char*)smem + SC_BYTES);    // [QT][QS_STRIDE]
    float* KVs = Qs + QT * QS_STRIDE;                 // [2][KT][KS_STRIDE]

    const int tid   = threadIdx.x;
    const int bh    = blockIdx.y;
    const int qbase = blockIdx.x * QT;

    const float qk_s = *qk_s_p;
    const float a_s  = *a_s_p;
    const float av_s = *av_s_p;

    const float* Qg = Q + ((size_t)bh * S_LEN + qbase) * HD;
    const float* Kg = K + (size_t)bh * S_LEN * HD;
    const float* Vg = V + (size_t)bh * S_LEN * HD;

    const u32 kvs_u32 = (u32)__cvta_generic_to_shared(KVs);

    // ---- prologue: async K tile 0 + Q tile ----
    {
        #pragma unroll
        for (int it = 0; it < 8; it++) {
            int lin = it * 256 + tid;
            int k  = lin >> 4;
            int dq = lin & 15;
            cp16(kvs_u32 + (u32)((k * KS_STRIDE + dq * 4) * 4), Kg + k * HD + dq * 4);
        }
        CP_COMMIT();
        #pragma unroll
        for (int it = 0; it < 2; it++) {
            int lin = it * 256 + tid;
            int q  = lin >> 4;
            int dq = lin & 15;
            float4 v = *(const float4*)(Qg + q * HD + dq * 4);
            *(float4*)(Qs + q * QS_STRIDE + dq * 4) = v;
        }
    }

    // ===== Phase 1: S codes = q8((Q K^T)/8), f32x2 chains ascending d ========
    {
        const int tk = tid & 31;
        const int tq = tid >> 5;
        const int q0 = tq * 4;

        for (int kt = 0; kt < S_LEN / KT; kt++) {
            const int cur = kt & 1;
            if (kt < 7) {
                const float* src = Kg + (kt + 1) * KT * HD;
                u32 dst = kvs_u32 + (u32)((1 - cur) * KV_TILE * 4);
                #pragma unroll
                for (int it = 0; it < 8; it++) {
                    int lin = it * 256 + tid;
                    int k  = lin >> 4;
                    int dq = lin & 15;
                    cp16(dst + (u32)((k * KS_STRIDE + dq * 4) * 4), src + k * HD + dq * 4);
                }
                CP_COMMIT();
                CP_WAIT1();
            } else {
                CP_WAIT0();
            }
            __syncthreads();

            const float* Kt = KVs + cur * KV_TILE;

            ull acc2[2][4];   // q-row pairs (q0,q0+1) and (q0+2,q0+3) x 4 k-cols
            #pragma unroll
            for (int p = 0; p < 2; p++)
                #pragma unroll
                for (int j = 0; j < 4; j++) acc2[p][j] = pack2(0.f, 0.f);

            #pragma unroll
            for (int d = 0; d < HD; d += 4) {
                float4 qv[4], kv[4];
                #pragma unroll
                for (int i = 0; i < 4; i++)
                    qv[i] = *(const float4*)(Qs + (q0 + i) * QS_STRIDE + d);
                #pragma unroll
                for (int j = 0; j < 4; j++)
                    kv[j] = *(const float4*)(Kt + (tk + 32 * j) * KS_STRIDE + d);

                #define P1STEP(c) { \
                    ull A0 = pack2(qv[0].c, qv[1].c); \
                    ull A1 = pack2(qv[2].c, qv[3].c); \
                    _Pragma("unroll") \
                    for (int j = 0; j < 4; j++) { \
                        ull B = pack2(kv[j].c, kv[j].c); \
                        acc2[0][j] = ffma2(A0, B, acc2[0][j]); \
                        acc2[1][j] = ffma2(A1, B, acc2[1][j]); \
                    } }
                P1STEP(x) P1STEP(y) P1STEP(z) P1STEP(w)
                #undef P1STEP
            }

            #pragma unroll
            for (int p = 0; p < 2; p++)
                #pragma unroll
                for (int j = 0; j < 4; j++) {
                    float lo, hi;
                    unpack2(acc2[p][j], lo, hi);
                    int col = kt * KT + tk + 32 * j;
                    SCc[(q0 + 2 * p    ) * SCB + col] = (char)q8(lo * 0.125f, qk_s);
                    SCc[(q0 + 2 * p + 1) * SCB + col] = (char)q8(hi * 0.125f, qk_s);
                }
            __syncthreads();
        }
    }

    // ===== Phase 2: softmax + quantize, fully in registers ===================
    {
        const int lane = tid & 31;
        const int w    = tid >> 5;           // 8 warps, 4 rows each

        #pragma unroll
        for (int r = 0; r < 4; r++) {
            char* row = SCc + (4 * w + r) * SCB;
            const int4* rp = (const int4*)(row + 32 * lane);
            int4 wa = rp[0], wb = rp[1];
            int wd[8] = {wa.x, wa.y, wa.z, wa.w, wb.x, wb.y, wb.z, wb.w};

            float e[32];                     // dequantized scores, then exps
            #pragma unroll
            for (int k = 0; k < 8; k++)
                #pragma unroll
                for (int b = 0; b < 4; b++)
                    e[k * 4 + b] = b2f(wd[k], b) * qk_s;   // == fq value bitwise

            float m = e[0];
            #pragma unroll
            for (int i = 1; i < 32; i++) m = fmaxf(m, e[i]);
            #pragma unroll
            for (int o = 16; o; o >>= 1) m = fmaxf(m, __shfl_xor_sync(0xffffffffu, m, o));

            #pragma unroll
            for (int i = 0; i < 32; i++) e[i] = expf(e[i] - m);   // __nv_expf

            // sacred sum tree: halves-first within the contiguous 32-block...
            float t16[16];
            #pragma unroll
            for (int i = 0; i < 16; i++) t16[i] = e[i] + e[i + 16];
            #pragma unroll
            for (int h = 8; h >= 1; h >>= 1)
                #pragma unroll
                for (int i = 0; i < 8; i++)
                    if (i < h) t16[i] = t16[i] + t16[i + h];
            float p = t16[0];
            // ...then halves-first over the 32 block partials (xor tree)
            #pragma unroll
            for (int o = 16; o; o >>= 1) p += __shfl_xor_sync(0xffffffffu, p, o);
            const float sum_f = p;

            int out[8];
            #pragma unroll
            for (int k = 0; k < 8; k++) {
                int wk = 0;
                #pragma unroll
                for (int b = 0; b < 4; b++) {
                    float pr = __fdiv_rn(e[k * 4 + b], sum_f);
                    int n = q8(pr, a_s);
                    wk |= (n & 0xff) << (8 * b);
                }
                out[k] = wk;
            }
            int4* wp = (int4*)(row + 32 * lane);
            wp[0] = make_int4(out[0], out[1], out[2], out[3]);
            wp[1] = make_int4(out[4], out[5], out[6], out[7]);
        }
    }

    // ---- prologue phase 3: loader warps fetch V tile 0 ----
    if (tid >= 128) {
        const int lt = tid - 128;
        #pragma unroll
        for (int it = 0; it < 16; it++) {
            int lin = it * 128 + lt;
            int k  = lin >> 4;
            int dq = lin & 15;
            cp16(kvs_u32 + (u32)((k * KS_STRIDE + dq * 4) * 4), Vg + k * HD + dq * 4);
        }
        CP_COMMIT();
    }

    // ===== Phase 3: O = fq(A V), f32x2 chains ascending t, 4q x 4d ==========
    {
        const int td = tid & 15;
        const int tq = tid >> 4;             // valid for tid<128
        const int d0 = td * 4;
        const int q0 = tq * 4;

        ull acc[4][2];
        #pragma unroll
        for (int i = 0; i < 4; i++) { acc[i][0] = pack2(0.f, 0.f); acc[i][1] = pack2(0.f, 0.f); }

        for (int vt = 0; vt < S_LEN / KT; vt++) {
            const int cur = vt & 1;
            if (tid >= 128 && vt < 7) {
                const int lt = tid - 128;
                const float* src = Vg + (vt + 1) * KT * HD;
                u32 dst = kvs_u32 + (u32)((1 - cur) * KV_TILE * 4);
                #pragma unroll
                for (int it = 0; it < 16; it++) {
                    int lin = it * 128 + lt;
                    int k  = lin >> 4;
                    int dq = lin & 15;
                    cp16(dst + (u32)((k * KS_STRIDE + dq * 4) * 4), src + k * HD + dq * 4);
                }
                CP_COMMIT();
            }
            if (vt < 7) CP_WAIT1(); else CP_WAIT0();
            __syncthreads();

            if (tid < 128) {
                const float* Vt = KVs + cur * KV_TILE;
                const char* r0 = SCc + (q0 + 0) * SCB + vt * KT;
                const char* r1 = SCc + (q0 + 1) * SCB + vt * KT;
                const char* r2 = SCc + (q0 + 2) * SCB + vt * KT;
                const char* r3 = SCc + (q0 + 3) * SCB + vt * KT;
                #pragma unroll 4
                for (int k4 = 0; k4 < KT / 4; k4++) {
                    int w0 = *(const int*)(r0 + 4 * k4);   // broadcast LDS.32
                    int w1 = *(const int*)(r1 + 4 * k4);
                    int w2 = *(const int*)(r2 + 4 * k4);
                    int w3 = *(const int*)(r3 + 4 * k4);
                    #pragma unroll
                    for (int b = 0; b < 4; b++) {
                        int kk = k4 * 4 + b;
                        float a0 = b2f(w0, b) * a_s;   // == fq prob bitwise
                        float a1 = b2f(w1, b) * a_s;
                        float a2 = b2f(w2, b) * a_s;
                        float a3 = b2f(w3, b) * a_s;
                        ull A0 = pack2(a0, a0), A1 = pack2(a1, a1);
                        ull A2 = pack2(a2, a2), A3 = pack2(a3, a3);
                        ulonglong2 vv = *(const ulonglong2*)(Vt + kk * KS_STRIDE + d0);
                        acc[0][0] = ffma2(A0, vv.x, acc[0][0]);
                        acc[0][1] = ffma2(A0, vv.y, acc[0][1]);
                        acc[1][0] = ffma2(A1, vv.x, acc[1][0]);
                        acc[1][1] = ffma2(A1, vv.y, acc[1][1]);
                        acc[2][0] = ffma2(A2, vv.x, acc[2][0]);
                        acc[2][1] = ffma2(A2, vv.y, acc[2][1]);
                        acc[3][0] = ffma2(A3, vv.x, acc[3][0]);
                        acc[3][1] = ffma2(A3, vv.y, acc[3][1]);
                    }
                }
            }
            __syncthreads();
        }

        if (tid < 128) {
            #pragma unroll
            for (int i = 0; i < 4; i++) {
                float v0, v1, v2, v3;
                unpack2(acc[i][0], v0, v1);
                unpack2(acc[i][1], v2, v3);
                float4 res;
                res.x = (float)q8(v0, av_s) * av_s;
                res.y = (float)q8(v1, av_s) * av_s;
                res.z = (float)q8(v2, av_s) * av_s;
                res.w = (float)q8(v3, av_s) * av_s;
                float* Og = O + ((size_t)bh * S_LEN + qbase + q0 + i) * HD + d0;
                *(float4*)Og = res;
            }
        }
    }
}

extern "C" void kernel_launch(void* const* d_in, const int* in_sizes, int n_in,
                              void* d_out, int out_size) {
    const float* Q    = (const float*)d_in[0];
    const float* K    = (const float*)d_in[1];
    const float* V    = (const float*)d_in[2];
    const float* qk_s = (const float*)d_in[3];
    const float* a_s  = (const float*)d_in[4];
    const float* av_s = (const float*)d_in[5];
    float* O = (float*)d_out;

    const int BH = in_sizes[0] / (S_LEN * HD);   // 128

    cudaFuncSetAttribute(attn_qat_kernel,
                         cudaFuncAttributeMaxDynamicSharedMemorySize, SMEM_BYTES);

    dim3 grid(S_LEN / QT, BH);
    attn_qat_kernel<<<grid, 256, SMEM_BYTES>>>(Q, K, V, qk_s, a_s, av_s, O);
}

// round 9
// speedup vs baseline: 1.5824x; 1.1562x over previous
#include <cuda_runtime.h>
#include <cstddef>
#include <cstdint>
#include <math.h>

// Quant-aware attention, bit-matched to the JAX/XLA reference (rel_err == 0.0).
// SACRED (do not reorder): QK/PV sequential fp32 FMA chains ascending over the
// contraction dim (f32x2 halves are independent IEEE chains); expf; softmax sum
// = halves-first tree within each contiguous 32-block then halves-first tree
// over the 32 block partials; IEEE-correct f32 divisions; rintf; clamp.
// R9: (a) per-V-tile A-dequant staging to f32 smem (bit-neutral, kills the 16x
// redundant I2F work); (b) Markstein 3-op correctly-rounded division with
// precomputed __frcp_rn reciprocals (bit-identical to div.rn.f32 for normals).

#define S_LEN 1024
#define HD 64
#define QT 32
#define KT 64             // K/V rows per smem tile (halved to fit A-stage)
#define SCB 1056          // SC row stride in BYTES (int8 codes)
#define QS_STRIDE 68      // floats
#define KS_STRIDE 68      // floats
#define AS_STRIDE 68      // floats, staged A row stride
#define KV_TILE  (KT*KS_STRIDE)          // floats
#define SC_BYTES (QT*SCB)                // 33792
#define SMEM_BYTES (SC_BYTES + 4*(QT*QS_STRIDE) + 4*(2*KV_TILE) + 4*(QT*AS_STRIDE))

typedef unsigned long long ull;
typedef unsigned int u32;

__device__ __forceinline__ ull ffma2(ull a, ull b, ull c) {
    ull d;
    asm("fma.rn.f32x2 %0, %1, %2, %3;" : "=l"(d) : "l"(a), "l"(b), "l"(c));
    return d;
}
__device__ __forceinline__ ull pack2(float x, float y) {
    ull r; asm("mov.b64 %0, {%1, %2};" : "=l"(r) : "f"(x), "f"(y)); return r;
}
__device__ __forceinline__ void unpack2(ull v, float& lo, float& hi) {
    asm("mov.b64 {%0, %1}, %2;" : "=f"(lo), "=f"(hi) : "l"(v));
}
__device__ __forceinline__ void cp16(u32 s, const void* g) {
    asm volatile("cp.async.cg.shared.global [%0], [%1], 16;" :: "r"(s), "l"(g));
}
#define CP_COMMIT() asm volatile("cp.async.commit_group;")
#define CP_WAIT1()  asm volatile("cp.async.wait_group 1;")
#define CP_WAIT0()  asm volatile("cp.async.wait_group 0;")

// Correctly-rounded x/s given y = __frcp_rn(s) (Markstein; bit == div.rn.f32
// for normal operands, which all our values are).
__device__ __forceinline__ float fdiv_fast(float x, float s, float y) {
    float q = __fmul_rn(x, y);
    float r = __fmaf_rn(-s, q, x);
    return __fmaf_rn(r, y, q);
}
// int8 code: n = clip(rint(x/s), -128, 127)
__device__ __forceinline__ int q8f(float x, float s, float y) {
    float r = rintf(fdiv_fast(x, s, y));
    r = fminf(fmaxf(r, -128.0f), 127.0f);
    return (int)r;
}
__device__ __forceinline__ float b2f(int w, int b) {
    return (float)((int)(signed char)(w >> (8 * b)));
}

__global__ __launch_bounds__(256, 2)
void attn_qat_kernel(const float* __restrict__ Q,
                     const float* __restrict__ K,
                     const float* __restrict__ V,
                     const float* __restrict__ qk_s_p,
                     const float* __restrict__ a_s_p,
                     const float* __restrict__ av_s_p,
                     float* __restrict__ O) {
    extern __shared__ float smem[];
    char*  SCc = (char*)smem;                           // [QT][SCB] int8 codes
    float* Qs  = (float*)((char*)smem + SC_BYTES);      // [QT][QS_STRIDE]
    float* KVs = Qs + QT * QS_STRIDE;                   // [2][KT][KS_STRIDE]
    float* As  = KVs + 2 * KV_TILE;                     // [QT][AS_STRIDE]

    const int tid   = threadIdx.x;
    const int bh    = blockIdx.y;
    const int qbase = blockIdx.x * QT;

    const float qk_s = *qk_s_p;
    const float a_s  = *a_s_p;
    const float av_s = *av_s_p;
    const float y_qk = __frcp_rn(qk_s);
    const float y_a  = __frcp_rn(a_s);
    const float y_av = __frcp_rn(av_s);

    const float* Qg = Q + ((size_t)bh * S_LEN + qbase) * HD;
    const float* Kg = K + (size_t)bh * S_LEN * HD;
    const float* Vg = V + (size_t)bh * S_LEN * HD;

    const u32 kvs_u32 = (u32)__cvta_generic_to_shared(KVs);

    // ---- prologue: async K tile 0 (64x64) + Q tile ----
    {
        #pragma unroll
        for (int it = 0; it < 4; it++) {                // 1024 float4 / 256 thr
            int lin = it * 256 + tid;
            int k  = lin >> 4;
            int dq = lin & 15;
            cp16(kvs_u32 + (u32)((k * KS_STRIDE + dq * 4) * 4), Kg + k * HD + dq * 4);
        }
        CP_COMMIT();
        #pragma unroll
        for (int it = 0; it < 2; it++) {
            int lin = it * 256 + tid;
            int q  = lin >> 4;
            int dq = lin & 15;
            float4 v = *(const float4*)(Qg + q * HD + dq * 4);
            *(float4*)(Qs + q * QS_STRIDE + dq * 4) = v;
        }
    }

    // ===== Phase 1: S codes = q8((Q K^T)/8), f32x2 chains ascending d ========
    {
        const int tk = tid & 31;
        const int tq = tid >> 5;
        const int q0 = tq * 4;

        for (int kt = 0; kt < S_LEN / KT; kt++) {       // 16 tiles of 64
            const int cur = kt & 1;
            if (kt < 15) {
                const float* src = Kg + (kt + 1) * KT * HD;
                u32 dst = kvs_u32 + (u32)((1 - cur) * KV_TILE * 4);
                #pragma unroll
                for (int it = 0; it < 4; it++) {
                    int lin = it * 256 + tid;
                    int k  = lin >> 4;
                    int dq = lin & 15;
                    cp16(dst + (u32)((k * KS_STRIDE + dq * 4) * 4), src + k * HD + dq * 4);
                }
                CP_COMMIT();
                CP_WAIT1();
            } else {
                CP_WAIT0();
            }
            __syncthreads();

            const float* Kt = KVs + cur * KV_TILE;

            ull acc2[2][2];  // q-pairs (q0,q0+1),(q0+2,q0+3) x k-cols {tk, tk+32}
            #pragma unroll
            for (int p = 0; p < 2; p++)
                #pragma unroll
                for (int j = 0; j < 2; j++) acc2[p][j] = pack2(0.f, 0.f);

            #pragma unroll
            for (int d = 0; d < HD; d += 4) {
                float4 qv[4], kv[2];
                #pragma unroll
                for (int i = 0; i < 4; i++)
                    qv[i] = *(const float4*)(Qs + (q0 + i) * QS_STRIDE + d);
                #pragma unroll
                for (int j = 0; j < 2; j++)
                    kv[j] = *(const float4*)(Kt + (tk + 32 * j) * KS_STRIDE + d);

                #define P1STEP(c) { \
                    ull A0 = pack2(qv[0].c, qv[1].c); \
                    ull A1 = pack2(qv[2].c, qv[3].c); \
                    _Pragma("unroll") \
                    for (int j = 0; j < 2; j++) { \
                        ull B = pack2(kv[j].c, kv[j].c); \
                        acc2[0][j] = ffma2(A0, B, acc2[0][j]); \
                        acc2[1][j] = ffma2(A1, B, acc2[1][j]); \
                    } }
                P1STEP(x) P1STEP(y) P1STEP(z) P1STEP(w)
                #undef P1STEP
            }

            #pragma unroll
            for (int p = 0; p < 2; p++)
                #pragma unroll
                for (int j = 0; j < 2; j++) {
                    float lo, hi;
                    unpack2(acc2[p][j], lo, hi);
                    int col = kt * KT + tk + 32 * j;
                    SCc[(q0 + 2 * p    ) * SCB + col] = (char)q8f(lo * 0.125f, qk_s, y_qk);
                    SCc[(q0 + 2 * p + 1) * SCB + col] = (char)q8f(hi * 0.125f, qk_s, y_qk);
                }
            __syncthreads();
        }
    }

    // ===== Phase 2: softmax + quantize, fully in registers ===================
    {
        const int lane = tid & 31;
        const int w    = tid >> 5;

        #pragma unroll
        for (int r = 0; r < 4; r++) {
            char* row = SCc + (4 * w + r) * SCB;
            const int4* rp = (const int4*)(row + 32 * lane);
            int4 wa = rp[0], wb = rp[1];
            int wd[8] = {wa.x, wa.y, wa.z, wa.w, wb.x, wb.y, wb.z, wb.w};

            float e[32];
            #pragma unroll
            for (int k = 0; k < 8; k++)
                #pragma unroll
                for (int b = 0; b < 4; b++)
                    e[k * 4 + b] = b2f(wd[k], b) * qk_s;   // bitwise fq value

            float m = e[0];
            #pragma unroll
            for (int i = 1; i < 32; i++) m = fmaxf(m, e[i]);
            #pragma unroll
            for (int o = 16; o; o >>= 1) m = fmaxf(m, __shfl_xor_sync(0xffffffffu, m, o));

            #pragma unroll
            for (int i = 0; i < 32; i++) e[i] = expf(e[i] - m);   // __nv_expf

            // sacred sum: halves-first within contiguous 32-block...
            float t16[16];
            #pragma unroll
            for (int i = 0; i < 16; i++) t16[i] = e[i] + e[i + 16];
            #pragma unroll
            for (int h = 8; h >= 1; h >>= 1)
                #pragma unroll
                for (int i = 0; i < 8; i++)
                    if (i < h) t16[i] = t16[i] + t16[i + h];
            float p = t16[0];
            #pragma unroll
            for (int o = 16; o; o >>= 1) p += __shfl_xor_sync(0xffffffffu, p, o);
            const float sum_f = p;
            const float y_sum = __frcp_rn(sum_f);

            int out[8];
            #pragma unroll
            for (int k = 0; k < 8; k++) {
                int wk = 0;
                #pragma unroll
                for (int b = 0; b < 4; b++) {
                    float pr = fdiv_fast(e[k * 4 + b], sum_f, y_sum);
                    int n = q8f(pr, a_s, y_a);
                    wk |= (n & 0xff) << (8 * b);
                }
                out[k] = wk;
            }
            int4* wp = (int4*)(row + 32 * lane);
            wp[0] = make_int4(out[0], out[1], out[2], out[3]);
            wp[1] = make_int4(out[4], out[5], out[6], out[7]);
        }
    }
    __syncthreads();                                    // SC codes final

    // ---- prologue phase 3: loader warps fetch V tile 0 ----
    if (tid >= 128) {
        const int lt = tid - 128;
        #pragma unroll
        for (int it = 0; it < 8; it++) {                // 1024 float4 / 128 thr
            int lin = it * 128 + lt;
            int k  = lin >> 4;
            int dq = lin & 15;
            cp16(kvs_u32 + (u32)((k * KS_STRIDE + dq * 4) * 4), Vg + k * HD + dq * 4);
        }
        CP_COMMIT();
    }

    // ===== Phase 3: O = fq(A V), f32x2 chains ascending t, staged A =========
    {
        const int td = tid & 15;
        const int tq = tid >> 4;             // valid for tid<128
        const int d0 = td * 4;
        const int q0 = tq * 4;
        const int srow = tid >> 3;           // staging: row 0..31
        const int sseg = tid & 7;            // staging: 8-value segment

        ull acc[4][2];
        #pragma unroll
        for (int i = 0; i < 4; i++) { acc[i][0] = pack2(0.f, 0.f); acc[i][1] = pack2(0.f, 0.f); }

        for (int vt = 0; vt < S_LEN / KT; vt++) {
            const int cur = vt & 1;

            // stage A slice: dequant 32x64 int8 codes -> f32 (8 per thread)
            {
                int2 w2 = *(const int2*)(SCc + srow * SCB + vt * KT + sseg * 8);
                float4 f0, f1;
                f0.x = b2f(w2.x, 0) * a_s; f0.y = b2f(w2.x, 1) * a_s;
                f0.z = b2f(w2.x, 2) * a_s; f0.w = b2f(w2.x, 3) * a_s;
                f1.x = b2f(w2.y, 0) * a_s; f1.y = b2f(w2.y, 1) * a_s;
                f1.z = b2f(w2.y, 2) * a_s; f1.w = b2f(w2.y, 3) * a_s;
                *(float4*)(As + srow * AS_STRIDE + sseg * 8)     = f0;
                *(float4*)(As + srow * AS_STRIDE + sseg * 8 + 4) = f1;
            }
            CP_WAIT0();                      // V(vt) arrived (no-op for compute)
            __syncthreads();

            if (tid < 128) {
                const float* Vt = KVs + cur * KV_TILE;
                #pragma unroll 2
                for (int k4 = 0; k4 < KT / 4; k4++) {
                    float4 a0 = *(const float4*)(As + (q0 + 0) * AS_STRIDE + k4 * 4);
                    float4 a1 = *(const float4*)(As + (q0 + 1) * AS_STRIDE + k4 * 4);
                    float4 a2 = *(const float4*)(As + (q0 + 2) * AS_STRIDE + k4 * 4);
                    float4 a3 = *(const float4*)(As + (q0 + 3) * AS_STRIDE + k4 * 4);

                    #define P3STEP(c, boff) { \
                        ulonglong2 vv = *(const ulonglong2*)(Vt + (k4 * 4 + boff) * KS_STRIDE + d0); \
                        ull A0 = pack2(a0.c, a0.c), A1 = pack2(a1.c, a1.c); \
                        ull A2 = pack2(a2.c, a2.c), A3 = pack2(a3.c, a3.c); \
                        acc[0][0] = ffma2(A0, vv.x, acc[0][0]); \
                        acc[0][1] = ffma2(A0, vv.y, acc[0][1]); \
                        acc[1][0] = ffma2(A1, vv.x, acc[1][0]); \
                        acc[1][1] = ffma2(A1, vv.y, acc[1][1]); \
                        acc[2][0] = ffma2(A2, vv.x, acc[2][0]); \
                        acc[2][1] = ffma2(A2, vv.y, acc[2][1]); \
                        acc[3][0] = ffma2(A3, vv.x, acc[3][0]); \
                        acc[3][1] = ffma2(A3, vv.y, acc[3][1]); }
                    P3STEP(x, 0) P3STEP(y, 1) P3STEP(z, 2) P3STEP(w, 3)
                    #undef P3STEP
                }
            } else if (vt < 15) {            // loader warps prefetch V(vt+1)
                const int lt = tid - 128;
                const float* src = Vg + (vt + 1) * KT * HD;
                u32 dst = kvs_u32 + (u32)((1 - cur) * KV_TILE * 4);
                #pragma unroll
                for (int it = 0; it < 8; it++) {
                    int lin = it * 128 + lt;
                    int k  = lin >> 4;
                    int dq = lin & 15;
                    cp16(dst + (u32)((k * KS_STRIDE + dq * 4) * 4), src + k * HD + dq * 4);
                }
                CP_COMMIT();
            }
            __syncthreads();                 // guards As rewrite + KV buf reuse
        }

        if (tid < 128) {
            #pragma unroll
            for (int i = 0; i < 4; i++) {
                float v0, v1, v2, v3;
                unpack2(acc[i][0], v0, v1);
                unpack2(acc[i][1], v2, v3);
                float4 res;
                res.x = (float)q8f(v0, av_s, y_av) * av_s;
                res.y = (float)q8f(v1, av_s, y_av) * av_s;
                res.z = (float)q8f(v2, av_s, y_av) * av_s;
                res.w = (float)q8f(v3, av_s, y_av) * av_s;
                float* Og = O + ((size_t)bh * S_LEN + qbase + q0 + i) * HD + d0;
                *(float4*)Og = res;
            }
        }
    }
}

extern "C" void kernel_launch(void* const* d_in, const int* in_sizes, int n_in,
                              void* d_out, int out_size) {
    const float* Q    = (const float*)d_in[0];
    const float* K    = (const float*)d_in[1];
    const float* V    = (const float*)d_in[2];
    const float* qk_s = (const float*)d_in[3];
    const float* a_s  = (const float*)d_in[4];
    const float* av_s = (const float*)d_in[5];
    float* O = (float*)d_out;

    const int BH = in_sizes[0] / (S_LEN * HD);   // 128

    cudaFuncSetAttribute(attn_qat_kernel,
                         cudaFuncAttributeMaxDynamicSharedMemorySize, SMEM_BYTES);

    dim3 grid(S_LEN / QT, BH);
    attn_qat_kernel<<<grid, 256, SMEM_BYTES>>>(Q, K, V, qk_s, a_s, av_s, O);
}